// round 2
// baseline (speedup 1.0000x reference)
#include <cuda_runtime.h>
#include <stdint.h>

// Fp8Unpadding: gather valid rows out of 256-padded groups.
// inp:       [total_padded, 4096] fp32  (d_in[0])
// m_splits:  [n_groups] int32           (d_in[1])  <-- JAX x64-disabled downcasts int64->int32
// out:       [sum(m_splits), 4096] fp32
//
// Pure bandwidth problem: 1 block per output row, float4 copies.

static constexpr int HIDDEN = 4096;
static constexpr int VECS_PER_ROW = HIDDEN / 4;  // 1024 float4 per row

__global__ void __launch_bounds__(256, 8)
unpad_gather_kernel(const float4* __restrict__ in,
                    const int* __restrict__ m_splits,
                    int n_groups,
                    float4* __restrict__ out)
{
    const long long row = blockIdx.x;

    // Find (group, offset) for this output row. n_groups is tiny (8);
    // these loads are L1-resident after the first touch.
    long long cum = 0;        // cumulative valid rows (output offset)
    long long pad_off = 0;    // cumulative padded rows (input offset)
    long long src_row = 0;
#pragma unroll 1
    for (int g = 0; g < n_groups; ++g) {
        const long long m = (long long)m_splits[g];
        if (row < cum + m) {
            src_row = pad_off + (row - cum);
            break;
        }
        cum += m;
        pad_off += ((m + 255LL) >> 8) << 8;  // pad to 256
    }

    const float4* __restrict__ src = in  + src_row * VECS_PER_ROW;
    float4*       __restrict__ dst = out + row     * VECS_PER_ROW;

    // 1024 float4 per row, 256 threads -> 4 vec copies per thread, coalesced.
#pragma unroll
    for (int i = threadIdx.x; i < VECS_PER_ROW; i += 256) {
        dst[i] = src[i];
    }
}

extern "C" void kernel_launch(void* const* d_in, const int* in_sizes, int n_in,
                              void* d_out, int out_size)
{
    const float4* in       = (const float4*)d_in[0];
    const int*    m_splits = (const int*)d_in[1];
    const int     n_groups = in_sizes[1];

    float4* out = (float4*)d_out;
    const int n_rows = out_size / HIDDEN;  // total valid rows

    unpad_gather_kernel<<<n_rows, 256>>>(in, m_splits, n_groups, out);
}